// round 16
// baseline (speedup 1.0000x reference)
#include <cuda_runtime.h>
#include <cuda_fp16.h>
#include <math.h>
#include <stdint.h>

#define BSZ   32768
#define IND   256
#define NFEAT 8
#define EDIM  16
#define VOCAB 100000
#define DNUM  4
#define WID2  512

// ------------------------- scratch (device globals; no allocs) ----------
__device__ __align__(16) __half g_gate_h[(size_t)BSZ * IND];          // fp16 gate_in
__device__ __align__(16) __half g_g1h[(size_t)DNUM * BSZ * 512];      // g1_0(256)|g1_1(128)|g1_2(128,pad)
__device__ __align__(16) __half g_gt[(size_t)DNUM * BSZ * 448];       // gate0(256)|gate1(128)|gate2(64)
__device__ __align__(16) __half g_hh[(size_t)DNUM * BSZ * 448];       // h0(256)|h1(128)|h2(64)
__device__ float g_hpre[(size_t)DNUM * BSZ * 256];                    // fp32 h_pre (reused per layer)
__device__ float g_sums3[3][2 * DNUM * 256];
__device__ float g_bcat[DNUM * WID2];                                 // concat bias for wideB
__device__ __align__(16) __half g_wh[1400000];                        // packed fp16 weights

// ------------------------- helpers --------------------------------------
__device__ __forceinline__ void mma_f16(float c[4], const unsigned a[4],
                                        unsigned b0, unsigned b1) {
    asm volatile(
        "mma.sync.aligned.m16n8k16.row.col.f32.f16.f16.f32 "
        "{%0,%1,%2,%3}, {%4,%5,%6,%7}, {%8,%9}, {%0,%1,%2,%3};"
        : "+f"(c[0]), "+f"(c[1]), "+f"(c[2]), "+f"(c[3])
        : "r"(a[0]), "r"(a[1]), "r"(a[2]), "r"(a[3]), "r"(b0), "r"(b1));
}

__device__ __forceinline__ void ldsm_x4(unsigned r[4], uint32_t addr) {
    asm volatile("ldmatrix.sync.aligned.m8n8.x4.shared.b16 {%0,%1,%2,%3}, [%4];"
                 : "=r"(r[0]), "=r"(r[1]), "=r"(r[2]), "=r"(r[3]) : "r"(addr));
}

__device__ __forceinline__ uint32_t smem_u32(const void* p) {
    uint32_t a;
    asm("{ .reg .u64 t; cvta.to.shared.u64 t, %1; cvt.u32.u64 %0, t; }" : "=r"(a) : "l"(p));
    return a;
}

__device__ __forceinline__ void cp16(uint32_t dst, const void* src) {
    asm volatile("cp.async.cg.shared.global [%0], [%1], 16;" :: "r"(dst), "l"(src));
}
#define CP_COMMIT() asm volatile("cp.async.commit_group;" ::: "memory")
__device__ __forceinline__ void cp_wait_n(int n) {
    if (n <= 0)      asm volatile("cp.async.wait_group 0;" ::: "memory");
    else if (n == 1) asm volatile("cp.async.wait_group 1;" ::: "memory");
    else             asm volatile("cp.async.wait_group 2;" ::: "memory");
}

// ------------------------- weight prep: fp16 + k32 fragment-pack --------
// k = 32kp + 16kt + kr: tig=(kr&7)>>1, pos=(kr&1)|((kr>>3)<<1)
// dst half index: ((d*(K/32)+kp)*ldn + colOff + n)*32 + tig*8 + kt*4 + pos
struct TSeg { const float* src; __half* dst; int K; int N; int ldn; int colOff; int total; };
struct TArgs { TSeg seg[10]; };
__global__ void prep_weights(TArgs a) {
    int s = blockIdx.y;
    int i = blockIdx.x * 256 + threadIdx.x;
    TSeg sg = a.seg[s];
    if (i >= sg.total) return;
    int KN = sg.K * sg.N;
    int d = i / KN, r = i % KN;
    int k = r / sg.N, n = r % sg.N;
    int kp = k >> 5, kk = k & 31;
    int kt = kk >> 4, kr = kk & 15;
    int tig = (kr & 7) >> 1;
    int pos = (kr & 1) | ((kr >> 3) << 1);
    size_t dst = ((size_t)(d * (sg.K >> 5) + kp) * sg.ldn + sg.colOff + n) * 32
               + tig * 8 + kt * 4 + pos;
    sg.dst[dst] = sg.src ? __float2half_rn(sg.src[i]) : __half(0.0f);
}

// --------------- embedding gather (+ zero sums, + wideB-bias concat) ----
__global__ void embed_kernel(const int* __restrict__ id_idx,
                             const int* __restrict__ agn_idx,
                             const float* __restrict__ id_tab,
                             const float* __restrict__ agn_tab,
                             const float* __restrict__ mb0,
                             const float* __restrict__ g11,
                             const float* __restrict__ g12) {
    int t = blockIdx.x * blockDim.x + threadIdx.x;
    if (t < 3 * 2 * DNUM * 256) ((float*)g_sums3)[t] = 0.0f;
    if (t < DNUM * WID2) {
        int d = t / WID2, c = t % WID2;
        float v;
        if      (c < 256) v = mb0[d * 256 + c];
        else if (c < 384) v = g11[d * 128 + (c - 256)];
        else if (c < 448) v = g12[d * 64  + (c - 384)];
        else              v = 0.0f;
        g_bcat[t] = v;
    }
    if (t >= BSZ * 64) return;
    int b = t >> 6;
    int j = (t & 63) << 2;
    const int*   idx = id_idx;
    const float* tab = id_tab;
    int jj = j;
    if (j >= 128) { idx = agn_idx; tab = agn_tab; jj = j - 128; }
    int f = jj >> 4, e = jj & 15;
    int v = idx[b * NFEAT + f];
    float4 val = *(const float4*)(tab + ((size_t)f * VOCAB + v) * EDIM + e);
    __half* p = g_gate_h + (size_t)b * IND + j;
    *(__half2*)(p)     = __floats2half2_rn(val.x, val.y);
    *(__half2*)(p + 2) = __floats2half2_rn(val.z, val.w);
}

// ------------------------- per-layer fp16 GEMM ---------------------------
// EPI 0: Cf := acc (fp32) + column stats into sums
// EPI 1: Ch := half(relu(acc))
// EPI 2: Ch := half(2*sigmoid(acc))
template <int BN, int EPI>
__global__ void __launch_bounds__(256, 2)
gemm_tc(const __half* __restrict__ A, size_t aDomStride, int lda,
        const __half* __restrict__ Wp,
        const float* __restrict__ bias,
        float* __restrict__ Cf,
        __half* __restrict__ Ch,
        float* __restrict__ sums,
        int K, int N) {
    constexpr int BM = 128;
    constexpr int WN = BN / 2;
    constexpr int NI = WN / 8;
    constexpr int ASTRIDE = 80;
    constexpr int ABYTES = BM * ASTRIDE;
    constexpr int BBYTES = BN * 64;
    constexpr int SB = ABYTES + BBYTES;
    constexpr int NS = 4;

    extern __shared__ __align__(16) char dynsm[];
    __shared__ float cs[BN], cq[BN];

    int d  = blockIdx.z;
    int bm = blockIdx.x * BM;
    int bn = blockIdx.y * BN;
    const __half* Ad = A + (size_t)d * aDomStride + (size_t)bm * lda;
    const __half* Bd = Wp + ((size_t)d * (K / 32) * N + bn) * 32;
    float*  Cfd = Cf ? Cf + ((size_t)d * BSZ + bm) * N + bn : nullptr;
    __half* Chd = Ch ? Ch + ((size_t)d * BSZ + bm) * N + bn : nullptr;

    int tid  = threadIdx.x;
    int lane = tid & 31, wid = tid >> 5;
    int gid  = lane >> 2, tig = lane & 3;
    int wm   = wid >> 1,  wn  = wid & 1;

    uint32_t sbase = smem_u32(dynsm);
    uint32_t lrow = lane & 15;
    uint32_t aFragOff = (wm * 32 + lrow) * ASTRIDE + (lane >> 4) * 16;

    float acc[2][NI][4] = {};

    auto stage = [&](int kp, int st) {
        uint32_t ab = sbase + st * SB;
#pragma unroll
        for (int i = 0; i < 2; i++) {
            int q = tid + i * 256;
            int row = q >> 2, seg = q & 3;
            cp16(ab + row * ASTRIDE + seg * 16, Ad + (size_t)row * lda + kp * 32 + seg * 8);
        }
        uint32_t bb = ab + ABYTES;
        const __half* Bq = Bd + (size_t)kp * N * 32;
#pragma unroll
        for (int i = 0; i < BN / 64; i++) {
            int q = tid + i * 256;
            cp16(bb + q * 16, Bq + q * 8);
        }
        CP_COMMIT();
    };

    const int NCH = K / 32;
    const int npro = NCH < (NS - 1) ? NCH : (NS - 1);
    for (int t = 0; t < npro; t++) stage(t, t);

    int st = 0, sslot = npro;
    for (int c = 0; c < NCH; c++) {
        int pend = NCH - 1 - c; if (pend > NS - 2) pend = NS - 2;
        cp_wait_n(pend);
        __syncthreads();

        uint32_t aS = sbase + st * SB + aFragOff;
        const char* Bbase = dynsm + st * SB + ABYTES;

        uint4 bq[NI];
#pragma unroll
        for (int ni = 0; ni < NI; ni++) {
            int cb = wn * WN + ni * 8 + gid;
            bq[ni] = *(const uint4*)(Bbase + cb * 64 + tig * 16);
        }
        unsigned af0[2][4], af1[2][4];
#pragma unroll
        for (int mi = 0; mi < 2; mi++) {
            ldsm_x4(af0[mi], aS + mi * 16 * ASTRIDE);
            ldsm_x4(af1[mi], aS + mi * 16 * ASTRIDE + 32);
        }
#pragma unroll
        for (int mi = 0; mi < 2; mi++)
#pragma unroll
            for (int ni = 0; ni < NI; ni++) {
                mma_f16(acc[mi][ni], af0[mi], bq[ni].x, bq[ni].y);
                mma_f16(acc[mi][ni], af1[mi], bq[ni].z, bq[ni].w);
            }

        if (c + NS - 1 < NCH) {
            stage(c + NS - 1, sslot);
            if (++sslot == NS) sslot = 0;
        }
        if (++st == NS) st = 0;
    }

    if (EPI == 0) {
        if (tid < BN) { cs[tid] = 0.0f; cq[tid] = 0.0f; }
        __syncthreads();
    }

    float colS[NI][2] = {}, colQ[NI][2] = {};

#pragma unroll
    for (int mi = 0; mi < 2; mi++) {
        int r0 = wm * 32 + mi * 16 + gid;
#pragma unroll
        for (int ni = 0; ni < NI; ni++) {
            int col = wn * WN + ni * 8 + 2 * tig;
            float b0 = bias[d * N + bn + col];
            float b1 = bias[d * N + bn + col + 1];
            float v0 = acc[mi][ni][0] + b0;
            float v1 = acc[mi][ni][1] + b1;
            float v2 = acc[mi][ni][2] + b0;
            float v3 = acc[mi][ni][3] + b1;
            if (EPI == 0) {
                colS[ni][0] += v0 + v2;      colS[ni][1] += v1 + v3;
                colQ[ni][0] += v0 * v0 + v2 * v2;
                colQ[ni][1] += v1 * v1 + v3 * v3;
                *(float2*)(Cfd + (size_t)r0 * N + col)       = make_float2(v0, v1);
                *(float2*)(Cfd + (size_t)(r0 + 8) * N + col) = make_float2(v2, v3);
            }
            if (EPI == 1) {
                *(__half2*)(Chd + (size_t)r0 * N + col) =
                    __floats2half2_rn(fmaxf(v0, 0.0f), fmaxf(v1, 0.0f));
                *(__half2*)(Chd + (size_t)(r0 + 8) * N + col) =
                    __floats2half2_rn(fmaxf(v2, 0.0f), fmaxf(v3, 0.0f));
            }
            if (EPI == 2) {
                *(__half2*)(Chd + (size_t)r0 * N + col) = __floats2half2_rn(
                    2.0f / (1.0f + expf(-v0)), 2.0f / (1.0f + expf(-v1)));
                *(__half2*)(Chd + (size_t)(r0 + 8) * N + col) = __floats2half2_rn(
                    2.0f / (1.0f + expf(-v2)), 2.0f / (1.0f + expf(-v3)));
            }
        }
    }

    if (EPI == 0) {
#pragma unroll
        for (int ni = 0; ni < NI; ni++)
#pragma unroll
            for (int c2 = 0; c2 < 2; c2++) {
                float sv = colS[ni][c2], qv = colQ[ni][c2];
                sv += __shfl_xor_sync(0xffffffffu, sv, 16);
                sv += __shfl_xor_sync(0xffffffffu, sv, 8);
                sv += __shfl_xor_sync(0xffffffffu, sv, 4);
                qv += __shfl_xor_sync(0xffffffffu, qv, 16);
                qv += __shfl_xor_sync(0xffffffffu, qv, 8);
                qv += __shfl_xor_sync(0xffffffffu, qv, 4);
                if (gid == 0) {
                    int c = wn * WN + ni * 8 + 2 * tig + c2;
                    atomicAdd(&cs[c], sv);
                    atomicAdd(&cq[c], qv);
                }
            }
        __syncthreads();
        if (tid < BN) {
            atomicAdd(&sums[d * 256 + bn + tid], cs[tid]);
            atomicAdd(&sums[DNUM * 256 + d * 256 + bn + tid], cq[tid]);
        }
    }
}

// ------------------------- wideB GEMM ------------------------------------
// A = gate_in, W packed wide (ldn=512), K=256, 4 N-tiles of 128:
// tiles 0-1: mlp0 -> fp32 h_pre + stats; tile2 -> g1_1; tile3 -> g1_2 (+pad)
__global__ void __launch_bounds__(256, 2)
gemm_wideB(const __half* __restrict__ A,
           const __half* __restrict__ Wp,
           float* __restrict__ hpre,
           __half* __restrict__ g1_1,
           __half* __restrict__ g1_2,
           float* __restrict__ sums) {
    constexpr int BM = 128, NI = 8;
    constexpr int ASTRIDE = 80;
    constexpr int ABYTES = BM * ASTRIDE;
    constexpr int BBYTES = 128 * 64;
    constexpr int SB = ABYTES + BBYTES;
    constexpr int NS = 4;
    constexpr int KW = 256, NCH = KW / 32;

    extern __shared__ __align__(16) char dynsm[];
    __shared__ float cs[128], cq[128];

    int d  = blockIdx.z;
    int bm = blockIdx.x * BM;
    int ty = blockIdx.y;
    int gcBase = ty * 128;
    const __half* Ad = A + (size_t)bm * KW;
    const __half* Bd = Wp + ((size_t)d * NCH * WID2 + gcBase) * 32;

    int tid  = threadIdx.x;
    int lane = tid & 31, wid = tid >> 5;
    int gid  = lane >> 2, tig = lane & 3;
    int wm   = wid >> 1,  wn  = wid & 1;

    uint32_t sbase = smem_u32(dynsm);
    uint32_t lrow = lane & 15;
    uint32_t aFragOff = (wm * 32 + lrow) * ASTRIDE + (lane >> 4) * 16;

    float acc[2][NI][4] = {};

    auto stage = [&](int kp, int st) {
        uint32_t ab = sbase + st * SB;
#pragma unroll
        for (int i = 0; i < 2; i++) {
            int q = tid + i * 256;
            int row = q >> 2, seg = q & 3;
            cp16(ab + row * ASTRIDE + seg * 16, Ad + (size_t)row * KW + kp * 32 + seg * 8);
        }
        uint32_t bb = ab + ABYTES;
        const __half* Bq = Bd + (size_t)kp * WID2 * 32;
#pragma unroll
        for (int i = 0; i < 2; i++) {
            int q = tid + i * 256;
            cp16(bb + q * 16, Bq + q * 8);
        }
        CP_COMMIT();
    };

    stage(0, 0); stage(1, 1); stage(2, 2);

    int st = 0, sslot = 3;
    for (int c = 0; c < NCH; c++) {
        int pend = NCH - 1 - c; if (pend > NS - 2) pend = NS - 2;
        cp_wait_n(pend);
        __syncthreads();

        uint32_t aS = sbase + st * SB + aFragOff;
        const char* Bbase = dynsm + st * SB + ABYTES;

        uint4 bq[NI];
#pragma unroll
        for (int ni = 0; ni < NI; ni++) {
            int cb = wn * 64 + ni * 8 + gid;
            bq[ni] = *(const uint4*)(Bbase + cb * 64 + tig * 16);
        }
        unsigned af0[2][4], af1[2][4];
#pragma unroll
        for (int mi = 0; mi < 2; mi++) {
            ldsm_x4(af0[mi], aS + mi * 16 * ASTRIDE);
            ldsm_x4(af1[mi], aS + mi * 16 * ASTRIDE + 32);
        }
#pragma unroll
        for (int mi = 0; mi < 2; mi++)
#pragma unroll
            for (int ni = 0; ni < NI; ni++) {
                mma_f16(acc[mi][ni], af0[mi], bq[ni].x, bq[ni].y);
                mma_f16(acc[mi][ni], af1[mi], bq[ni].z, bq[ni].w);
            }

        if (c + NS - 1 < NCH) {
            stage(c + NS - 1, sslot);
            if (++sslot == NS) sslot = 0;
        }
        if (++st == NS) st = 0;
    }

    bool isMlp = (ty < 2);
    if (isMlp) {
        if (tid < 128) { cs[tid] = 0.0f; cq[tid] = 0.0f; }
        __syncthreads();
    }
    __half* hd = (ty == 2) ? g1_1 : g1_2;

    float colS[NI][2] = {}, colQ[NI][2] = {};

#pragma unroll
    for (int mi = 0; mi < 2; mi++) {
        int r0 = wm * 32 + mi * 16 + gid;
#pragma unroll
        for (int ni = 0; ni < NI; ni++) {
            int col = wn * 64 + ni * 8 + 2 * tig;
            int gc = gcBase + col;
            float b0 = g_bcat[d * WID2 + gc];
            float b1 = g_bcat[d * WID2 + gc + 1];
            float v0 = acc[mi][ni][0] + b0;
            float v1 = acc[mi][ni][1] + b1;
            float v2 = acc[mi][ni][2] + b0;
            float v3 = acc[mi][ni][3] + b1;
            if (isMlp) {
                colS[ni][0] += v0 + v2;      colS[ni][1] += v1 + v3;
                colQ[ni][0] += v0 * v0 + v2 * v2;
                colQ[ni][1] += v1 * v1 + v3 * v3;
                float* p0 = hpre + ((size_t)d * BSZ + bm + r0) * 256 + gc;
                float* p1 = hpre + ((size_t)d * BSZ + bm + r0 + 8) * 256 + gc;
                *(float2*)p0 = make_float2(v0, v1);
                *(float2*)p1 = make_float2(v2, v3);
            } else {
                __half* p0 = hd + ((size_t)d * BSZ + bm + r0) * 128 + col;
                __half* p1 = hd + ((size_t)d * BSZ + bm + r0 + 8) * 128 + col;
                *(__half2*)p0 = __floats2half2_rn(fmaxf(v0, 0.0f), fmaxf(v1, 0.0f));
                *(__half2*)p1 = __floats2half2_rn(fmaxf(v2, 0.0f), fmaxf(v3, 0.0f));
            }
        }
    }

    if (isMlp) {
#pragma unroll
        for (int ni = 0; ni < NI; ni++)
#pragma unroll
            for (int c2 = 0; c2 < 2; c2++) {
                float sv = colS[ni][c2], qv = colQ[ni][c2];
                sv += __shfl_xor_sync(0xffffffffu, sv, 16);
                sv += __shfl_xor_sync(0xffffffffu, sv, 8);
                sv += __shfl_xor_sync(0xffffffffu, sv, 4);
                qv += __shfl_xor_sync(0xffffffffu, qv, 16);
                qv += __shfl_xor_sync(0xffffffffu, qv, 8);
                qv += __shfl_xor_sync(0xffffffffu, qv, 4);
                if (gid == 0) {
                    int c = wn * 64 + ni * 8 + 2 * tig + c2;
                    atomicAdd(&cs[c], sv);
                    atomicAdd(&cq[c], qv);
                }
            }
        __syncthreads();
        if (tid < 128) {
            atomicAdd(&sums[d * 256 + gcBase + tid], cs[tid]);
            atomicAdd(&sums[DNUM * 256 + d * 256 + gcBase + tid], cq[tid]);
        }
    }
}

// ------------------------- BN apply + gate (elementwise) ----------------
// h = half( relu(hpre*sc + sh) * gate )
__global__ void bn_apply_gate(const float* __restrict__ Hp, const __half* __restrict__ G,
                              __half* __restrict__ H,
                              const float* __restrict__ sums,
                              const float* __restrict__ bng,
                              const float* __restrict__ bnb, int N) {
    size_t t = (size_t)blockIdx.x * blockDim.x + threadIdx.x;
    size_t total4 = (size_t)DNUM * BSZ * N / 4;
    if (t >= total4) return;
    size_t e = t * 4;
    int c = (int)(e % N);
    int d = (int)(e / ((size_t)BSZ * N));
    float4 hp = *(const float4*)(Hp + e);
    __half2 g01 = *(const __half2*)(G + e);
    __half2 g23 = *(const __half2*)(G + e + 2);
    float r[4] = {hp.x, hp.y, hp.z, hp.w};
    float gg[4] = {__half2float(g01.x), __half2float(g01.y),
                   __half2float(g23.x), __half2float(g23.y)};
#pragma unroll
    for (int j = 0; j < 4; j++) {
        int idx = d * 256 + c + j;
        float mean = sums[idx] * (1.0f / BSZ);
        float var  = sums[DNUM * 256 + idx] * (1.0f / BSZ) - mean * mean;
        float sc   = bng[d * N + c + j] * rsqrtf(var + 1e-5f);
        float sh   = bnb[d * N + c + j] - mean * sc;
        r[j] = fmaxf(r[j] * sc + sh, 0.0f) * gg[j];
    }
    *(__half2*)(H + e)     = __floats2half2_rn(r[0], r[1]);
    *(__half2*)(H + e + 2) = __floats2half2_rn(r[2], r[3]);
}

// ------------------------- final head -----------------------------------
__global__ void final_kernel(const __half* __restrict__ H,
                             const int* __restrict__ dom,
                             const float* __restrict__ finW,
                             const float* __restrict__ finb,
                             float* __restrict__ out) {
    int warp = (blockIdx.x * blockDim.x + threadIdx.x) >> 5;
    int lane = threadIdx.x & 31;
    if (warp >= BSZ) return;
    int d = dom[warp];
    const __half* h = H + ((size_t)d * BSZ + warp) * 64;
    const float* w = finW + d * 64;
    float s = __half2float(h[lane]) * w[lane] + __half2float(h[lane + 32]) * w[lane + 32];
#pragma unroll
    for (int o = 16; o > 0; o >>= 1) s += __shfl_down_sync(0xffffffffu, s, o);
    if (lane == 0) out[warp] = 1.0f / (1.0f + expf(-(s + finb[d])));
}

// ------------------------- dispatch helper ------------------------------
template <int EPI>
static void launch_gemm(cudaStream_t strm, const __half* A, size_t aStride, int lda,
                        const __half* Wp, const float* b, float* Cf, __half* Ch,
                        float* sums, int K, int N) {
    if (N >= 128) {
        constexpr int SM = 4 * (128 * 80 + 128 * 64);
        cudaFuncSetAttribute(gemm_tc<128, EPI>, cudaFuncAttributeMaxDynamicSharedMemorySize, SM);
        dim3 grid(BSZ / 128, N / 128, DNUM);
        gemm_tc<128, EPI><<<grid, 256, SM, strm>>>(A, aStride, lda, Wp, b, Cf, Ch, sums, K, N);
    } else {
        constexpr int SM = 4 * (128 * 80 + 64 * 64);
        cudaFuncSetAttribute(gemm_tc<64, EPI>, cudaFuncAttributeMaxDynamicSharedMemorySize, SM);
        dim3 grid(BSZ / 128, N / 64, DNUM);
        gemm_tc<64, EPI><<<grid, 256, SM, strm>>>(A, aStride, lda, Wp, b, Cf, Ch, sums, K, N);
    }
}

// ------------------------- launch --------------------------------------
extern "C" void kernel_launch(void* const* d_in, const int* in_sizes, int n_in,
                              void* d_out, int out_size) {
    const int*   id_idx    = (const int*)d_in[0];
    const int*   agn_idx   = (const int*)d_in[1];
    const int*   domain_id = (const int*)d_in[2];
    const float* id_tab    = (const float*)d_in[3];
    const float* agn_tab   = (const float*)d_in[4];
    const float* mlp_W[3]  = {(const float*)d_in[5],  (const float*)d_in[13], (const float*)d_in[21]};
    const float* mlp_b[3]  = {(const float*)d_in[6],  (const float*)d_in[14], (const float*)d_in[22]};
    const float* bn_g[3]   = {(const float*)d_in[7],  (const float*)d_in[15], (const float*)d_in[23]};
    const float* bn_b[3]   = {(const float*)d_in[8],  (const float*)d_in[16], (const float*)d_in[24]};
    const float* gW1[3]    = {(const float*)d_in[9],  (const float*)d_in[17], (const float*)d_in[25]};
    const float* gb1[3]    = {(const float*)d_in[10], (const float*)d_in[18], (const float*)d_in[26]};
    const float* gW2[3]    = {(const float*)d_in[11], (const float*)d_in[19], (const float*)d_in[27]};
    const float* gb2[3]    = {(const float*)d_in[12], (const float*)d_in[20], (const float*)d_in[28]};
    const float* finW      = (const float*)d_in[29];
    const float* finb      = (const float*)d_in[30];
    float*       out       = (float*)d_out;

    __half *p_gate_h, *p_g1h, *p_gt, *p_hh, *p_w;
    float *p_hpre, *p_sums;
    cudaGetSymbolAddress((void**)&p_gate_h, g_gate_h);
    cudaGetSymbolAddress((void**)&p_g1h, g_g1h);
    cudaGetSymbolAddress((void**)&p_gt, g_gt);
    cudaGetSymbolAddress((void**)&p_hh, g_hh);
    cudaGetSymbolAddress((void**)&p_hpre, g_hpre);
    cudaGetSymbolAddress((void**)&p_sums, g_sums3);
    cudaGetSymbolAddress((void**)&p_w, g_wh);

    static cudaStream_t s1 = nullptr;
    static cudaEvent_t evStart, evPrep, evWideA, evWideB, evGate[3];
    if (!s1) {
        cudaStreamCreateWithFlags(&s1, cudaStreamNonBlocking);
        cudaEventCreateWithFlags(&evStart, cudaEventDisableTiming);
        cudaEventCreateWithFlags(&evPrep, cudaEventDisableTiming);
        cudaEventCreateWithFlags(&evWideA, cudaEventDisableTiming);
        cudaEventCreateWithFlags(&evWideB, cudaEventDisableTiming);
        for (int i = 0; i < 3; i++) cudaEventCreateWithFlags(&evGate[i], cudaEventDisableTiming);
    }

    // buffers within globals
    __half* g1_0 = p_g1h;                                    // stride 256
    __half* g1_1 = p_g1h + (size_t)DNUM * BSZ * 256;         // stride 128
    __half* g1_2 = g1_1 + (size_t)DNUM * BSZ * 128;          // stride 128 (64 data + pad)
    __half* gt0 = p_gt;                                      // stride 256
    __half* gt1 = p_gt + (size_t)DNUM * BSZ * 256;           // stride 128
    __half* gt2 = gt1 + (size_t)DNUM * BSZ * 128;            // stride 64
    __half* h0 = p_hh;                                       // stride 256
    __half* h1 = p_hh + (size_t)DNUM * BSZ * 256;            // stride 128
    __half* h2 = h1 + (size_t)DNUM * BSZ * 128;              // stride 64

    // weight packs
    __half* wA = p_w;                                        // gW1_0: [D][8][256][32]
    size_t off = (size_t)DNUM * 8 * 256 * 32;
    __half* wB = p_w + off;  off += (size_t)DNUM * 8 * WID2 * 32;   // wideB
    __half* wG2_0 = p_w + off; off += (size_t)DNUM * 8 * 256 * 32;
    __half* wM1   = p_w + off; off += (size_t)DNUM * 8 * 128 * 32;
    __half* wG2_1 = p_w + off; off += (size_t)DNUM * 4 * 128 * 32;
    __half* wM2   = p_w + off; off += (size_t)DNUM * 4 * 64 * 32;
    __half* wG2_2 = p_w + off; off += (size_t)DNUM * 2 * 64 * 32;

    TArgs ta;
    int si = 0;
    ta.seg[si++] = {gW1[0],   wA,    256, 256, 256, 0,   DNUM * 256 * 256};
    ta.seg[si++] = {mlp_W[0], wB,    256, 256, WID2, 0,   DNUM * 256 * 256};
    ta.seg[si++] = {gW1[1],   wB,    256, 128, WID2, 256, DNUM * 256 * 128};
    ta.seg[si++] = {gW1[2],   wB,    256, 64,  WID2, 384, DNUM * 256 * 64};
    ta.seg[si++] = {nullptr,  wB,    256, 64,  WID2, 448, DNUM * 256 * 64};
    ta.seg[si++] = {gW2[0],   wG2_0, 256, 256, 256, 0, DNUM * 256 * 256};
    ta.seg[si++] = {mlp_W[1], wM1,   256, 128, 128, 0, DNUM * 256 * 128};
    ta.seg[si++] = {gW2[1],   wG2_1, 128, 128, 128, 0, DNUM * 128 * 128};
    ta.seg[si++] = {mlp_W[2], wM2,   128, 64,  64,  0, DNUM * 128 * 64};
    ta.seg[si++] = {gW2[2],   wG2_2, 64,  64,  64,  0, DNUM * 64 * 64};

    int maxn = 0;
    for (int s = 0; s < 10; s++) if (ta.seg[s].total > maxn) maxn = ta.seg[s].total;

    float* sums0 = p_sums;
    float* sums1 = p_sums + 2 * DNUM * 256;
    float* sums2 = p_sums + 4 * DNUM * 256;

    // ---- fork: s1 = prep + gate GEMMs ----------------------------------
    cudaEventRecord(evStart, 0);
    cudaStreamWaitEvent(s1, evStart, 0);
    dim3 rg((maxn + 255) / 256, 10);
    prep_weights<<<rg, 256, 0, s1>>>(ta);
    cudaEventRecord(evPrep, s1);

    // s0: embed -> (wait prep) wideA -> wideB
    embed_kernel<<<(BSZ * 64 + 255) / 256, 256>>>(id_idx, agn_idx, id_tab, agn_tab,
                                                  mlp_b[0], gb1[1], gb1[2]);
    cudaStreamWaitEvent(0, evPrep, 0);

    // wideA: g1_0 = relu(gate_in @ gW1_0)
    launch_gemm<1>(0, p_gate_h, 0, 256, wA, gb1[0], nullptr, g1_0, nullptr, 256, 256);
    cudaEventRecord(evWideA, 0);

    // wideB: mlp0 h_pre + stats, g1_1, g1_2
    {
        constexpr int SM = 4 * (128 * 80 + 128 * 64);
        cudaFuncSetAttribute(gemm_wideB, cudaFuncAttributeMaxDynamicSharedMemorySize, SM);
        dim3 grid(BSZ / 128, 4, DNUM);
        gemm_wideB<<<grid, 256, SM>>>(p_gate_h, wB, p_hpre, g1_1, g1_2, sums0);
    }
    cudaEventRecord(evWideB, 0);

    // s1: gate0 (overlaps wideB), then gate1, gate2
    cudaStreamWaitEvent(s1, evWideA, 0);
    launch_gemm<2>(s1, g1_0, (size_t)BSZ * 256, 256, wG2_0, gb2[0], nullptr, gt0, nullptr, 256, 256);
    cudaEventRecord(evGate[0], s1);
    cudaStreamWaitEvent(s1, evWideB, 0);
    launch_gemm<2>(s1, g1_1, (size_t)BSZ * 128, 128, wG2_1, gb2[1], nullptr, gt1, nullptr, 128, 128);
    cudaEventRecord(evGate[1], s1);
    launch_gemm<2>(s1, g1_2, (size_t)BSZ * 128, 128, wG2_2, gb2[2], nullptr, gt2, nullptr, 64, 64);
    cudaEventRecord(evGate[2], s1);

    // s0 main chain
    cudaStreamWaitEvent(0, evGate[0], 0);
    {
        size_t tot4 = (size_t)DNUM * BSZ * 256 / 4;
        bn_apply_gate<<<(unsigned)((tot4 + 255) / 256), 256>>>(p_hpre, gt0, h0, sums0, bn_g[0], bn_b[0], 256);
    }
    launch_gemm<0>(0, h0, (size_t)BSZ * 256, 256, wM1, mlp_b[1], p_hpre, nullptr, sums1, 256, 128);
    cudaStreamWaitEvent(0, evGate[1], 0);
    {
        size_t tot4 = (size_t)DNUM * BSZ * 128 / 4;
        bn_apply_gate<<<(unsigned)((tot4 + 255) / 256), 256>>>(p_hpre, gt1, h1, sums1, bn_g[1], bn_b[1], 128);
    }
    launch_gemm<0>(0, h1, (size_t)BSZ * 128, 128, wM2, mlp_b[2], p_hpre, nullptr, sums2, 128, 64);
    cudaStreamWaitEvent(0, evGate[2], 0);
    {
        size_t tot4 = (size_t)DNUM * BSZ * 64 / 4;
        bn_apply_gate<<<(unsigned)((tot4 + 255) / 256), 256>>>(p_hpre, gt2, h2, sums2, bn_g[2], bn_b[2], 64);
    }
    final_kernel<<<BSZ / 8, 256>>>(h2, domain_id, finW, finb, out);
}

// round 17
// speedup vs baseline: 1.1972x; 1.1972x over previous
#include <cuda_runtime.h>
#include <cuda_fp16.h>
#include <math.h>
#include <stdint.h>

#define BSZ   32768
#define IND   256
#define NFEAT 8
#define EDIM  16
#define VOCAB 100000
#define DNUM  4

// ------------------------- scratch (device globals; no allocs) ----------
__device__ __align__(16) __half g_gate_h[(size_t)BSZ * IND];          // fp16 gate_in
__device__ __align__(16) __half g_g1h[(size_t)DNUM * BSZ * 448];      // fp16 g1 (per-layer)
__device__ __align__(16) __half g_hh[(size_t)DNUM * BSZ * 256];       // fp16 h
__device__ __align__(16) __half g_hpre[(size_t)DNUM * BSZ * 256];     // fp16 h_pre
__device__ float g_sums3[3][2 * DNUM * 256];
__device__ __align__(16) __half g_wh[1400000];                        // packed fp16 weights

// ------------------------- helpers --------------------------------------
__device__ __forceinline__ void mma_f16(float c[4], const unsigned a[4],
                                        unsigned b0, unsigned b1) {
    asm volatile(
        "mma.sync.aligned.m16n8k16.row.col.f32.f16.f16.f32 "
        "{%0,%1,%2,%3}, {%4,%5,%6,%7}, {%8,%9}, {%0,%1,%2,%3};"
        : "+f"(c[0]), "+f"(c[1]), "+f"(c[2]), "+f"(c[3])
        : "r"(a[0]), "r"(a[1]), "r"(a[2]), "r"(a[3]), "r"(b0), "r"(b1));
}

__device__ __forceinline__ void ldsm_x4(unsigned r[4], uint32_t addr) {
    asm volatile("ldmatrix.sync.aligned.m8n8.x4.shared.b16 {%0,%1,%2,%3}, [%4];"
                 : "=r"(r[0]), "=r"(r[1]), "=r"(r[2]), "=r"(r[3]) : "r"(addr));
}

__device__ __forceinline__ uint32_t smem_u32(const void* p) {
    uint32_t a;
    asm("{ .reg .u64 t; cvta.to.shared.u64 t, %1; cvt.u32.u64 %0, t; }" : "=r"(a) : "l"(p));
    return a;
}

__device__ __forceinline__ void cp16(uint32_t dst, const void* src) {
    asm volatile("cp.async.cg.shared.global [%0], [%1], 16;" :: "r"(dst), "l"(src));
}
#define CP_COMMIT() asm volatile("cp.async.commit_group;" ::: "memory")
__device__ __forceinline__ void cp_wait_n(int n) {
    if (n <= 0)      asm volatile("cp.async.wait_group 0;" ::: "memory");
    else if (n == 1) asm volatile("cp.async.wait_group 1;" ::: "memory");
    else             asm volatile("cp.async.wait_group 2;" ::: "memory");
}

// ------------------------- weight prep: fp16 + k32 fragment-pack --------
// k = 32kp + 16kt + kr: tig=(kr&7)>>1, pos=(kr&1)|((kr>>3)<<1)
// dst half index: ((d*(K/32)+kp)*N + n)*32 + tig*8 + kt*4 + pos
struct TSeg { const float* src; __half* dst; int K; int N; int total; };
struct TArgs { TSeg seg[9]; };
__global__ void prep_weights(TArgs a) {
    int s = blockIdx.y;
    int i = blockIdx.x * 256 + threadIdx.x;
    TSeg sg = a.seg[s];
    if (i >= sg.total) return;
    int KN = sg.K * sg.N;
    int d = i / KN, r = i % KN;
    int k = r / sg.N, n = r % sg.N;
    int kp = k >> 5, kk = k & 31;
    int kt = kk >> 4, kr = kk & 15;
    int tig = (kr & 7) >> 1;
    int pos = (kr & 1) | ((kr >> 3) << 1);
    size_t dst = ((size_t)(d * (sg.K >> 5) + kp) * sg.N + n) * 32 + tig * 8 + kt * 4 + pos;
    sg.dst[dst] = __float2half_rn(sg.src[i]);
}

// ------------------------- embedding gather (+ zero sums) ---------------
__global__ void embed_kernel(const int* __restrict__ id_idx,
                             const int* __restrict__ agn_idx,
                             const float* __restrict__ id_tab,
                             const float* __restrict__ agn_tab) {
    int t = blockIdx.x * blockDim.x + threadIdx.x;
    if (t < 3 * 2 * DNUM * 256) ((float*)g_sums3)[t] = 0.0f;
    if (t >= BSZ * 64) return;
    int b = t >> 6;
    int j = (t & 63) << 2;
    const int*   idx = id_idx;
    const float* tab = id_tab;
    int jj = j;
    if (j >= 128) { idx = agn_idx; tab = agn_tab; jj = j - 128; }
    int f = jj >> 4, e = jj & 15;
    int v = idx[b * NFEAT + f];
    float4 val = *(const float4*)(tab + ((size_t)f * VOCAB + v) * EDIM + e);
    __half* p = g_gate_h + (size_t)b * IND + j;
    *(__half2*)(p)     = __floats2half2_rn(val.x, val.y);
    *(__half2*)(p + 2) = __floats2half2_rn(val.z, val.w);
}

// ------------------------- fp16 tensor-core GEMM -------------------------
// acc[d] = A[d] (BSZ x K, fp16) @ W(packed fp16)[d] + bias[d]   (fp32 accum)
// EPI 0: Hpre := half(acc)  + column stats (from fp32 acc) into sums
// EPI 1: Ch := half(relu(acc))
// EPI 3: gate = 2*sigmoid(acc); Ch := half(relu(Hpre*sc + sh) * gate)
// BM=128, BK=32, 4-stage cp.async ring. 8 warps (4m x 2n), warp tile 32 x (BN/2).
template <int BN, int EPI>
__global__ void __launch_bounds__(256, 2)
gemm_tc(const __half* __restrict__ A, size_t aDomStride,
        const __half* __restrict__ Wp,
        const float* __restrict__ bias,
        __half* __restrict__ Hpre,
        __half* __restrict__ Ch,
        float* __restrict__ sums,
        const float* __restrict__ bng,
        const float* __restrict__ bnb,
        int K, int N) {
    constexpr int BM = 128;
    constexpr int WN = BN / 2;               // 64 or 32
    constexpr int NI = WN / 8;               // 8 or 4
    constexpr int ASTRIDE = 80;              // bytes per A row (64 data + 16 pad)
    constexpr int ABYTES = BM * ASTRIDE;
    constexpr int BBYTES = BN * 64;
    constexpr int SB = ABYTES + BBYTES;
    constexpr int NS = 4;

    extern __shared__ __align__(16) char dynsm[];
    __shared__ float cs[BN], cq[BN];

    int d  = blockIdx.z;
    int bm = blockIdx.x * BM;
    int bn = blockIdx.y * BN;
    const __half* Ad = A + (size_t)d * aDomStride + (size_t)bm * K;
    const __half* Bd = Wp + ((size_t)d * (K / 32) * N + bn) * 32;
    __half* Hpd = Hpre ? Hpre + ((size_t)d * BSZ + bm) * N + bn : nullptr;
    __half* Chd = Ch ? Ch + ((size_t)d * BSZ + bm) * N + bn : nullptr;

    int tid  = threadIdx.x;
    int lane = tid & 31, wid = tid >> 5;
    int gid  = lane >> 2, tig = lane & 3;
    int wm   = wid >> 1,  wn  = wid & 1;

    uint32_t sbase = smem_u32(dynsm);
    uint32_t lrow = lane & 15;
    uint32_t aFragOff = (wm * 32 + lrow) * ASTRIDE + (lane >> 4) * 16;

    float acc[2][NI][4] = {};

    auto stage = [&](int kp, int st) {
        uint32_t ab = sbase + st * SB;
#pragma unroll
        for (int i = 0; i < 2; i++) {
            int q = tid + i * 256;
            int row = q >> 2, seg = q & 3;
            cp16(ab + row * ASTRIDE + seg * 16, Ad + (size_t)row * K + kp * 32 + seg * 8);
        }
        uint32_t bb = ab + ABYTES;
        const __half* Bq = Bd + (size_t)kp * N * 32;
#pragma unroll
        for (int i = 0; i < BN / 64; i++) {
            int q = tid + i * 256;
            cp16(bb + q * 16, Bq + q * 8);
        }
        CP_COMMIT();
    };

    const int NCH = K / 32;
    const int npro = NCH < (NS - 1) ? NCH : (NS - 1);
    for (int t = 0; t < npro; t++) stage(t, t);

    int st = 0, sslot = npro;
    for (int c = 0; c < NCH; c++) {
        int pend = NCH - 1 - c; if (pend > NS - 2) pend = NS - 2;
        cp_wait_n(pend);
        __syncthreads();

        uint32_t aS = sbase + st * SB + aFragOff;
        const char* Bbase = dynsm + st * SB + ABYTES;

        uint4 bq[NI];
#pragma unroll
        for (int ni = 0; ni < NI; ni++) {
            int cb = wn * WN + ni * 8 + gid;
            bq[ni] = *(const uint4*)(Bbase + cb * 64 + tig * 16);
        }
        unsigned af0[2][4], af1[2][4];
#pragma unroll
        for (int mi = 0; mi < 2; mi++) {
            ldsm_x4(af0[mi], aS + mi * 16 * ASTRIDE);
            ldsm_x4(af1[mi], aS + mi * 16 * ASTRIDE + 32);
        }
#pragma unroll
        for (int mi = 0; mi < 2; mi++)
#pragma unroll
            for (int ni = 0; ni < NI; ni++) {
                mma_f16(acc[mi][ni], af0[mi], bq[ni].x, bq[ni].y);
                mma_f16(acc[mi][ni], af1[mi], bq[ni].z, bq[ni].w);
            }

        if (c + NS - 1 < NCH) {
            stage(c + NS - 1, sslot);
            if (++sslot == NS) sslot = 0;
        }
        if (++st == NS) st = 0;
    }

    if (EPI == 0) {
        if (tid < BN) { cs[tid] = 0.0f; cq[tid] = 0.0f; }
        __syncthreads();
    }
    if (EPI == 3) {
        if (tid < BN) {
            int idxc = d * 256 + bn + tid;
            float mean = sums[idxc] * (1.0f / BSZ);
            float var  = sums[DNUM * 256 + idxc] * (1.0f / BSZ) - mean * mean;
            float sc   = bng[d * N + bn + tid] * rsqrtf(var + 1e-5f);
            cs[tid] = sc;
            cq[tid] = bnb[d * N + bn + tid] - mean * sc;
        }
        __syncthreads();
    }

    float colS[NI][2] = {}, colQ[NI][2] = {};

#pragma unroll
    for (int mi = 0; mi < 2; mi++) {
        int r0 = wm * 32 + mi * 16 + gid;
#pragma unroll
        for (int ni = 0; ni < NI; ni++) {
            int col = wn * WN + ni * 8 + 2 * tig;
            float b0 = bias[d * N + bn + col];
            float b1 = bias[d * N + bn + col + 1];
            float v0 = acc[mi][ni][0] + b0;
            float v1 = acc[mi][ni][1] + b1;
            float v2 = acc[mi][ni][2] + b0;
            float v3 = acc[mi][ni][3] + b1;
            if (EPI == 0) {
                colS[ni][0] += v0 + v2;      colS[ni][1] += v1 + v3;
                colQ[ni][0] += v0 * v0 + v2 * v2;
                colQ[ni][1] += v1 * v1 + v3 * v3;
                *(__half2*)(Hpd + (size_t)r0 * N + col)       = __floats2half2_rn(v0, v1);
                *(__half2*)(Hpd + (size_t)(r0 + 8) * N + col) = __floats2half2_rn(v2, v3);
            }
            if (EPI == 1) {
                *(__half2*)(Chd + (size_t)r0 * N + col) =
                    __floats2half2_rn(fmaxf(v0, 0.0f), fmaxf(v1, 0.0f));
                *(__half2*)(Chd + (size_t)(r0 + 8) * N + col) =
                    __floats2half2_rn(fmaxf(v2, 0.0f), fmaxf(v3, 0.0f));
            }
            if (EPI == 3) {
                float g0 = 2.0f / (1.0f + expf(-v0));
                float g1 = 2.0f / (1.0f + expf(-v1));
                float g2 = 2.0f / (1.0f + expf(-v2));
                float g3 = 2.0f / (1.0f + expf(-v3));
                __half2 h01 = *(__half2*)(Hpd + (size_t)r0 * N + col);
                __half2 h23 = *(__half2*)(Hpd + (size_t)(r0 + 8) * N + col);
                float sc0 = cs[col], sh0 = cq[col];
                float sc1 = cs[col + 1], sh1 = cq[col + 1];
                *(__half2*)(Chd + (size_t)r0 * N + col) = __floats2half2_rn(
                    fmaxf(__half2float(h01.x) * sc0 + sh0, 0.0f) * g0,
                    fmaxf(__half2float(h01.y) * sc1 + sh1, 0.0f) * g1);
                *(__half2*)(Chd + (size_t)(r0 + 8) * N + col) = __floats2half2_rn(
                    fmaxf(__half2float(h23.x) * sc0 + sh0, 0.0f) * g2,
                    fmaxf(__half2float(h23.y) * sc1 + sh1, 0.0f) * g3);
            }
        }
    }

    if (EPI == 0) {
#pragma unroll
        for (int ni = 0; ni < NI; ni++)
#pragma unroll
            for (int c2 = 0; c2 < 2; c2++) {
                float sv = colS[ni][c2], qv = colQ[ni][c2];
                sv += __shfl_xor_sync(0xffffffffu, sv, 16);
                sv += __shfl_xor_sync(0xffffffffu, sv, 8);
                sv += __shfl_xor_sync(0xffffffffu, sv, 4);
                qv += __shfl_xor_sync(0xffffffffu, qv, 16);
                qv += __shfl_xor_sync(0xffffffffu, qv, 8);
                qv += __shfl_xor_sync(0xffffffffu, qv, 4);
                if (gid == 0) {
                    int c = wn * WN + ni * 8 + 2 * tig + c2;
                    atomicAdd(&cs[c], sv);
                    atomicAdd(&cq[c], qv);
                }
            }
        __syncthreads();
        if (tid < BN) {
            atomicAdd(&sums[d * 256 + bn + tid], cs[tid]);
            atomicAdd(&sums[DNUM * 256 + d * 256 + bn + tid], cq[tid]);
        }
    }
}

// ------------------------- final head -----------------------------------
__global__ void final_kernel(const __half* __restrict__ H,
                             const int* __restrict__ dom,
                             const float* __restrict__ finW,
                             const float* __restrict__ finb,
                             float* __restrict__ out) {
    int warp = (blockIdx.x * blockDim.x + threadIdx.x) >> 5;
    int lane = threadIdx.x & 31;
    if (warp >= BSZ) return;
    int d = dom[warp];
    const __half* h = H + ((size_t)d * BSZ + warp) * 64;
    const float* w = finW + d * 64;
    float s = __half2float(h[lane]) * w[lane] + __half2float(h[lane + 32]) * w[lane + 32];
#pragma unroll
    for (int o = 16; o > 0; o >>= 1) s += __shfl_down_sync(0xffffffffu, s, o);
    if (lane == 0) out[warp] = 1.0f / (1.0f + expf(-(s + finb[d])));
}

// ------------------------- dispatch helper ------------------------------
template <int EPI>
static void launch_gemm(cudaStream_t strm, const __half* A, size_t aStride,
                        const __half* Wp, const float* b, __half* Hpre, __half* Ch,
                        float* sums, const float* bng, const float* bnb, int K, int N) {
    if (N >= 128) {
        constexpr int SM = 4 * (128 * 80 + 128 * 64);    // 73728
        cudaFuncSetAttribute(gemm_tc<128, EPI>, cudaFuncAttributeMaxDynamicSharedMemorySize, SM);
        dim3 grid(BSZ / 128, N / 128, DNUM);
        gemm_tc<128, EPI><<<grid, 256, SM, strm>>>(A, aStride, Wp, b, Hpre, Ch, sums, bng, bnb, K, N);
    } else {
        constexpr int SM = 4 * (128 * 80 + 64 * 64);     // 57344
        cudaFuncSetAttribute(gemm_tc<64, EPI>, cudaFuncAttributeMaxDynamicSharedMemorySize, SM);
        dim3 grid(BSZ / 128, N / 64, DNUM);
        gemm_tc<64, EPI><<<grid, 256, SM, strm>>>(A, aStride, Wp, b, Hpre, Ch, sums, bng, bnb, K, N);
    }
}

// ------------------------- launch --------------------------------------
extern "C" void kernel_launch(void* const* d_in, const int* in_sizes, int n_in,
                              void* d_out, int out_size) {
    const int*   id_idx    = (const int*)d_in[0];
    const int*   agn_idx   = (const int*)d_in[1];
    const int*   domain_id = (const int*)d_in[2];
    const float* id_tab    = (const float*)d_in[3];
    const float* agn_tab   = (const float*)d_in[4];
    const float* mlp_W[3]  = {(const float*)d_in[5],  (const float*)d_in[13], (const float*)d_in[21]};
    const float* mlp_b[3]  = {(const float*)d_in[6],  (const float*)d_in[14], (const float*)d_in[22]};
    const float* bn_g[3]   = {(const float*)d_in[7],  (const float*)d_in[15], (const float*)d_in[23]};
    const float* bn_b[3]   = {(const float*)d_in[8],  (const float*)d_in[16], (const float*)d_in[24]};
    const float* gW1[3]    = {(const float*)d_in[9],  (const float*)d_in[17], (const float*)d_in[25]};
    const float* gb1[3]    = {(const float*)d_in[10], (const float*)d_in[18], (const float*)d_in[26]};
    const float* gW2[3]    = {(const float*)d_in[11], (const float*)d_in[19], (const float*)d_in[27]};
    const float* gb2[3]    = {(const float*)d_in[12], (const float*)d_in[20], (const float*)d_in[28]};
    const float* finW      = (const float*)d_in[29];
    const float* finb      = (const float*)d_in[30];
    float*       out       = (float*)d_out;

    __half *p_gate_h, *p_g1h, *p_hh, *p_hpre, *p_w;
    float *p_sums;
    cudaGetSymbolAddress((void**)&p_gate_h, g_gate_h);
    cudaGetSymbolAddress((void**)&p_g1h, g_g1h);
    cudaGetSymbolAddress((void**)&p_hh, g_hh);
    cudaGetSymbolAddress((void**)&p_hpre, g_hpre);
    cudaGetSymbolAddress((void**)&p_sums, g_sums3);
    cudaGetSymbolAddress((void**)&p_w, g_wh);

    // one-time host objects (no device memory involved)
    static cudaStream_t s1 = nullptr;
    static cudaEvent_t evStart, evEmbed, evPrep, evG1[3];
    if (!s1) {
        cudaStreamCreateWithFlags(&s1, cudaStreamNonBlocking);
        cudaEventCreateWithFlags(&evStart, cudaEventDisableTiming);
        cudaEventCreateWithFlags(&evEmbed, cudaEventDisableTiming);
        cudaEventCreateWithFlags(&evPrep, cudaEventDisableTiming);
        for (int i = 0; i < 3; i++) cudaEventCreateWithFlags(&evG1[i], cudaEventDisableTiming);
    }

    const int dims[4] = {256, 256, 128, 64};

    // packed fp16 weights
    __half* rW1[3]; __half* rW2[3]; __half* rWm[3];
    size_t off = 0;
    TArgs ta;
    int segi = 0, maxn = 0;
    for (int i = 0; i < 3; i++) {
        int N = dims[i + 1];
        rW1[i] = p_w + off;
        ta.seg[segi++] = {gW1[i], p_w + off, IND, N, DNUM * IND * N};           off += (size_t)DNUM * IND * N;
        rW2[i] = p_w + off;
        ta.seg[segi++] = {gW2[i], p_w + off, N, N, DNUM * N * N};               off += (size_t)DNUM * N * N;
        rWm[i] = p_w + off;
        ta.seg[segi++] = {mlp_W[i], p_w + off, dims[i], N, DNUM * dims[i] * N}; off += (size_t)DNUM * dims[i] * N;
    }
    for (int s = 0; s < 9; s++) if (ta.seg[s].total > maxn) maxn = ta.seg[s].total;

    // per-layer g1 buffers
    __half* g1buf[3];
    size_t goff = 0;
    for (int i = 0; i < 3; i++) {
        g1buf[i] = p_g1h + goff;
        goff += (size_t)DNUM * BSZ * dims[i + 1];
    }

    // ---- fork -----------------------------------------------------------
    cudaEventRecord(evStart, 0);
    cudaStreamWaitEvent(s1, evStart, 0);

    // s1: prep -> (evPrep) -> wait embed -> gW1 x3
    dim3 rg((maxn + 255) / 256, 9);
    prep_weights<<<rg, 256, 0, s1>>>(ta);
    cudaEventRecord(evPrep, s1);

    // s0: embed
    embed_kernel<<<(BSZ * 64 + 255) / 256, 256>>>(id_idx, agn_idx, id_tab, agn_tab);
    cudaEventRecord(evEmbed, 0);
    cudaStreamWaitEvent(s1, evEmbed, 0);

    for (int i = 0; i < 3; i++) {
        launch_gemm<1>(s1, p_gate_h, 0, rW1[i], gb1[i], nullptr, g1buf[i],
                       nullptr, nullptr, nullptr, IND, dims[i + 1]);
        cudaEventRecord(evG1[i], s1);
    }

    // ---- main stream: (wait prep) -> mlp0 -> [wait g1_i] gW2_i ... ------
    cudaStreamWaitEvent(0, evPrep, 0);

    const __half* hprev = nullptr;
    for (int i = 0; i < 3; i++) {
        int Kmlp = dims[i];
        int N    = dims[i + 1];
        float* sums = p_sums + (size_t)i * 2 * DNUM * 256;

        if (i == 0)
            launch_gemm<0>(0, p_gate_h, 0, rWm[i], mlp_b[i], p_hpre, nullptr,
                           sums, nullptr, nullptr, IND, N);
        else
            launch_gemm<0>(0, hprev, (size_t)BSZ * Kmlp, rWm[i], mlp_b[i], p_hpre, nullptr,
                           sums, nullptr, nullptr, Kmlp, N);

        cudaStreamWaitEvent(0, evG1[i], 0);
        launch_gemm<3>(0, g1buf[i], (size_t)BSZ * N, rW2[i], gb2[i], p_hpre, p_hh,
                       sums, bn_g[i], bn_b[i], N, N);

        hprev = p_hh;
    }

    final_kernel<<<BSZ / 8, 256>>>(hprev, domain_id, finW, finb, out);
}